// round 8
// baseline (speedup 1.0000x reference)
#include <cuda_runtime.h>
#include <cuda_fp16.h>

// QFM: out[b] = sum_f linear_w[x[b,f]+f*V] + bias
//             + 0.5 * sum_d ( (sum_f emb[b,f,d])^2 - sum_f emb[b,f,d]^2 )
// B=16384, F=39, V=100000, D=128, K=256, M=8, Q=16.
//
// R7: fp16 codebooks (prologue cvt) + shfl-free Phase B.
// One warp per row; lane t owns dims 4t..4t+3 (m = t>>2).
// Phase A: 10 coalesced code LDGs, then 4-lane OR-butterfly packs each
//          lane's own-m codes 4-per-register (byte s = feature 4c+s).
// Phase B: 39 independent gathers, address = BFE + IMAD only (no SHFL).

constexpr int F = 39;
constexpr int V = 100000;
constexpr int K = 256;
constexpr int D = 128;
constexpr int CB4 = F * K * D / 4;     // 319488 uint2 (4 halfs each)

__device__ uint2 g_cbh[CB4];           // fp16 codebooks, 2.56 MB scratch

__device__ __forceinline__ unsigned h2_bits(__half2 h) {
    return *reinterpret_cast<unsigned*>(&h);
}
__device__ __forceinline__ __half2 bits_h2(unsigned u) {
    return *reinterpret_cast<__half2*>(&u);
}

__global__ __launch_bounds__(256)
void cvt_kernel(const float4* __restrict__ src)
{
    const int i = blockIdx.x * blockDim.x + threadIdx.x;
    if (i < CB4) {
        const float4 v = src[i];
        uint2 o;
        o.x = h2_bits(__floats2half2_rn(v.x, v.y));
        o.y = h2_bits(__floats2half2_rn(v.z, v.w));
        g_cbh[i] = o;
    }
}

__global__ __launch_bounds__(256, 4)   // <=64 regs, 32 warps/SM
void qfm_kernel(const int*    __restrict__ x,          // (B, F)
                const int*    __restrict__ cb_index,   // (F*V, 8)
                const float*  __restrict__ linear_w,   // (F*V)
                const float*  __restrict__ linear_bias,// (1)
                float*        __restrict__ out,        // (B)
                int B)
{
    const unsigned FULL = 0xffffffffu;
    const int warp = (blockIdx.x * blockDim.x + threadIdx.x) >> 5;
    const int lane = threadIdx.x & 31;
    if (warp >= B) return;

    const int* xrow = x + warp * F;

    // Row indices: lanes 0..31 hold f=0..31, lanes 0..6 hold f=32..38.
    const int idx_lo = __ldcs(&xrow[lane]);
    const int idx_hi = (lane < F - 32) ? __ldcs(&xrow[32 + lane]) : 0;

    // Linear term (streaming, no reuse).
    float lin = __ldcs(&linear_w[lane * V + idx_lo]);
    if (lane < F - 32) lin += __ldcs(&linear_w[(32 + lane) * V + idx_hi]);

    // ---- Phase A: fetch all 39x8 codes (10 coalesced LDGs) and byte-pack.
    // Chunk c: lane (sub = lane&3, mseg = lane>>2) loads code mseg of
    // feature 4c+sub. OR-butterfly over the 4-lane group leaves every lane
    // holding packed codes of ITS m: codes[c] byte s = code(4c+s, lane>>2).
    unsigned codes[10];
    const int sub  = lane & 3;
    const int mseg = lane >> 2;
    #pragma unroll
    for (int c = 0; c < 10; ++c) {
        const int fl = 4 * c + sub;
        int idxf;
        if (c < 8) idxf = __shfl_sync(FULL, idx_lo, fl);
        else       idxf = __shfl_sync(FULL, idx_hi, fl - 32);
        unsigned cv = 0;
        if (fl < F)
            cv = (unsigned)__ldcs(&cb_index[((long long)fl * V + idxf) * 8 + mseg]);
        unsigned b = cv << (8 * sub);
        b |= __shfl_xor_sync(FULL, b, 1);
        b |= __shfl_xor_sync(FULL, b, 2);
        codes[c] = b;
    }

    // ---- Phase B: 39 independent 8B fp16 gathers; address is pure ALU.
    float4 s = make_float4(0.f, 0.f, 0.f, 0.f);
    float4 q = make_float4(0.f, 0.f, 0.f, 0.f);

    #pragma unroll
    for (int f = 0; f < F; ++f) {
        const unsigned code = (codes[f >> 2] >> (8 * (f & 3))) & 0xFFu;
        const uint2 raw = __ldg(&g_cbh[(f * K + code) * 32 + lane]);
        const float2 e0 = __half22float2(bits_h2(raw.x));
        const float2 e1 = __half22float2(bits_h2(raw.y));
        s.x += e0.x; s.y += e0.y; s.z += e1.x; s.w += e1.y;
        q.x = fmaf(e0.x, e0.x, q.x);
        q.y = fmaf(e0.y, e0.y, q.y);
        q.z = fmaf(e1.x, e1.x, q.z);
        q.w = fmaf(e1.y, e1.y, q.w);
    }

    float t = 0.5f * (fmaf(s.x, s.x, -q.x) +
                      fmaf(s.y, s.y, -q.y) +
                      fmaf(s.z, s.z, -q.z) +
                      fmaf(s.w, s.w, -q.w));
    t += lin;

    #pragma unroll
    for (int o = 16; o > 0; o >>= 1)
        t += __shfl_xor_sync(FULL, t, o);

    if (lane == 0) out[warp] = t + __ldg(linear_bias);
}

extern "C" void kernel_launch(void* const* d_in, const int* in_sizes, int n_in,
                              void* d_out, int out_size)
{
    const int*    x         = (const int*)   d_in[0];
    const float4* codebooks = (const float4*)d_in[1];
    const int*    cb_index  = (const int*)   d_in[2];
    const float*  linear_w  = (const float*) d_in[3];
    const float*  lbias     = (const float*) d_in[4];
    float*        out       = (float*)       d_out;

    const int B = out_size;

    // Prologue: fp32 -> fp16 codebook conversion (L2-resident, ~1 us).
    cvt_kernel<<<(CB4 + 255) / 256, 256>>>(codebooks);

    const int threads = 256;                       // 8 warps/block, 1 warp/row
    const int blocks  = (B * 32 + threads - 1) / threads;
    qfm_kernel<<<blocks, threads>>>(x, cb_index, linear_w, lbias, out, B);
}